// round 8
// baseline (speedup 1.0000x reference)
#include <cuda_runtime.h>
#include <cuda_bf16.h>
#include <cstdint>

// ---------------- problem constants ----------------
#define B_   2
#define N_   2048
#define E_   1024
#define H_   16
#define D_   64
#define SCALE_ 0.125f   // 64^-0.5

// ---------------- device scratch (no allocs allowed) ----------------
__device__ __nv_bfloat16 g_x_hi[(size_t)B_*N_*E_];
__device__ __nv_bfloat16 g_x_lo[(size_t)B_*N_*E_];
__device__ __nv_bfloat16 g_w_hi[(size_t)3*E_*E_];
__device__ __nv_bfloat16 g_w_lo[(size_t)3*E_*E_];
__device__ __nv_bfloat16 g_ow_hi[(size_t)E_*E_];
__device__ __nv_bfloat16 g_ow_lo[(size_t)E_*E_];
__device__ __nv_bfloat16 g_qh[(size_t)B_*H_*N_*D_];   // pre-scaled by SCALE_
__device__ __nv_bfloat16 g_ql[(size_t)B_*H_*N_*D_];
__device__ __nv_bfloat16 g_kh[(size_t)B_*H_*N_*D_];
__device__ __nv_bfloat16 g_kl[(size_t)B_*H_*N_*D_];
__device__ __nv_bfloat16 g_vh[(size_t)B_*H_*N_*D_];
__device__ __nv_bfloat16 g_vl[(size_t)B_*H_*N_*D_];
__device__ __nv_bfloat16 g_at_hi[(size_t)B_*N_*E_];
__device__ __nv_bfloat16 g_at_lo[(size_t)B_*N_*E_];

// =====================================================================
// helpers
// =====================================================================
__device__ __forceinline__ uint32_t smem_u32(const void* p) {
    uint32_t a;
    asm("{ .reg .u64 t; cvta.to.shared.u64 t, %1; cvt.u32.u64 %0, t; }" : "=r"(a) : "l"(p));
    return a;
}
__device__ __forceinline__ uint32_t sw128(uint32_t off) { return off ^ ((off >> 3) & 0x70); }
__device__ __forceinline__ uint32_t sw64(uint32_t off)  { return off ^ ((off >> 3) & 0x30); }

__device__ __forceinline__ void cpa16(uint32_t dst, const void* src) {
    asm volatile("cp.async.cg.shared.global [%0], [%1], 16;" :: "r"(dst), "l"(src));
}
#define CPC() asm volatile("cp.async.commit_group;" ::: "memory")
#define CPW(n) asm volatile("cp.async.wait_group %0;" :: "n"(n) : "memory")

__device__ __forceinline__ void ldsm4(uint32_t addr, uint32_t* r) {
    asm volatile("ldmatrix.sync.aligned.m8n8.x4.shared.b16 {%0,%1,%2,%3}, [%4];"
        : "=r"(r[0]), "=r"(r[1]), "=r"(r[2]), "=r"(r[3]) : "r"(addr));
}
__device__ __forceinline__ void ldsm4t(uint32_t addr, uint32_t* r) {
    asm volatile("ldmatrix.sync.aligned.m8n8.x4.trans.shared.b16 {%0,%1,%2,%3}, [%4];"
        : "=r"(r[0]), "=r"(r[1]), "=r"(r[2]), "=r"(r[3]) : "r"(addr));
}
__device__ __forceinline__ void mma16816(float* c, const uint32_t* a, uint32_t b0, uint32_t b1) {
    asm("mma.sync.aligned.m16n8k16.row.col.f32.bf16.bf16.f32 "
        "{%0,%1,%2,%3},{%4,%5,%6,%7},{%8,%9},{%0,%1,%2,%3};"
        : "+f"(c[0]), "+f"(c[1]), "+f"(c[2]), "+f"(c[3])
        : "r"(a[0]), "r"(a[1]), "r"(a[2]), "r"(a[3]), "r"(b0), "r"(b1));
}

__device__ __forceinline__ uint32_t pack_hi2(float v0, float v1) {
    __nv_bfloat162 h;
    h.x = __float2bfloat16(v0);
    h.y = __float2bfloat16(v1);
    return *(uint32_t*)&h;
}
__device__ __forceinline__ uint32_t pack_lo2(float v0, float v1) {
    __nv_bfloat16 h0 = __float2bfloat16(v0);
    __nv_bfloat16 h1 = __float2bfloat16(v1);
    __nv_bfloat162 l;
    l.x = __float2bfloat16(v0 - __bfloat162float(h0));
    l.y = __float2bfloat16(v1 - __bfloat162float(h1));
    return *(uint32_t*)&l;
}

// =====================================================================
// split kernel: fp32 -> bf16 hi + bf16 lo
// =====================================================================
template<int W>
__global__ void split_kernel(const float* __restrict__ src, int n4)
{
    __nv_bfloat16* hi = (W == 0) ? g_x_hi : (W == 1) ? g_w_hi : g_ow_hi;
    __nv_bfloat16* lo = (W == 0) ? g_x_lo : (W == 1) ? g_w_lo : g_ow_lo;
    int i = blockIdx.x * blockDim.x + threadIdx.x;
    if (i >= n4) return;
    float4 a = *(const float4*)&src[(size_t)i * 4];
    uint2 hv = {pack_hi2(a.x, a.y), pack_hi2(a.z, a.w)};
    uint2 lv = {pack_lo2(a.x, a.y), pack_lo2(a.z, a.w)};
    *(uint2*)&hi[(size_t)i * 4] = hv;
    *(uint2*)&lo[(size_t)i * 4] = lv;
}

// =====================================================================
// mma.sync GEMM (NT), bf16x3 split — 2 CTAs/SM config:
// BM=128, BN=128, BK=32 (64B rows, SW64 swizzle). 256 threads, 8 warps
// (2x4, warp tile 64x32). Double-buffered cp.async. ~120 regs/thread.
// MODE 0: epilogue -> g_q/k/v hi/lo (scatter [B,H,N,D], q scaled); MODE 1: fp32 C.
// =====================================================================
#define G_TILE 8192                  // 128 rows * 64B
#define G_STAGE (4 * G_TILE)         // Ah, Al, Bh, Bl = 32KB

extern __shared__ __align__(16) char dyn_smem[];

template<int MODE>
__global__ __launch_bounds__(256, 2)
void gemm_mma(const float* __restrict__ bias, float* __restrict__ C, int K, int Nout)
{
    const __nv_bfloat16* Ah = (MODE == 0) ? g_x_hi : g_at_hi;
    const __nv_bfloat16* Al = (MODE == 0) ? g_x_lo : g_at_lo;
    const __nv_bfloat16* Bh = (MODE == 0) ? g_w_hi : g_ow_hi;
    const __nv_bfloat16* Bl = (MODE == 0) ? g_w_lo : g_ow_lo;

    char* sm = (char*)(((uintptr_t)dyn_smem + 1023) & ~(uintptr_t)1023);
    uint32_t sb = smem_u32(sm);

    int tid = threadIdx.x;
    int lane = tid & 31;
    int wid = tid >> 5;              // 0..7
    int wm = wid >> 2;               // 0..1 -> rows wm*64
    int wn = wid & 3;                // 0..3 -> cols wn*32
    int m0 = blockIdx.y * 128;
    int n0 = blockIdx.x * 128;

    float acc[4][4][4];
#pragma unroll
    for (int a = 0; a < 4; a++)
#pragma unroll
        for (int b = 0; b < 4; b++)
#pragma unroll
            for (int c = 0; c < 4; c++) acc[a][b][c] = 0.f;

    // issue half h (0/1) of the loads for stage s, k-offset k0 (4 cpa16/thread)
    auto load_half = [&](int s, int k0, int h) {
        uint32_t st = sb + s * G_STAGE;
        int idx = tid + h * 256;            // 0..511
        int row = idx >> 2, seg = idx & 3;  // 128 rows x 4 segs of 16B
        uint32_t off = sw64((uint32_t)(row * 64 + seg * 16));
        size_t goA = (size_t)(m0 + row) * K + k0 + seg * 8;
        size_t goB = (size_t)(n0 + row) * K + k0 + seg * 8;
        cpa16(st + off, Ah + goA);
        cpa16(st + G_TILE + off, Al + goA);
        cpa16(st + 2 * G_TILE + off, Bh + goB);
        cpa16(st + 3 * G_TILE + off, Bl + goB);
    };

    const int NIT = K / 32;
    load_half(0, 0, 0);
    load_half(0, 0, 1);
    CPC();

    for (int it = 0; it < NIT; it++) {
        int s = it & 1;
        CPW(0);                 // stage s (issued during previous chunk) done
        __syncthreads();        // + all warps done reading stage s^1

        uint32_t aH = sb + s * G_STAGE;
        uint32_t aL = aH + G_TILE;
        uint32_t bHs = aH + 2 * G_TILE;
        uint32_t bLs = aH + 3 * G_TILE;
        bool pre = (it + 1 < NIT);

#pragma unroll
        for (int ks = 0; ks < 2; ks++) {
            if (pre) load_half(s ^ 1, (it + 1) * 32, ks);

            int koff = (ks * 16 + (lane >> 4) * 8) * 2;
            uint32_t ah[4][4], al[4][4];
#pragma unroll
            for (int tm = 0; tm < 4; tm++) {
                int ar = wm * 64 + tm * 16 + (lane & 15);
                uint32_t off = sw64((uint32_t)(ar * 64 + koff));
                ldsm4(aH + off, ah[tm]);
                ldsm4(aL + off, al[tm]);
            }
#pragma unroll
            for (int u = 0; u < 2; u++) {
                int br = wn * 32 + u * 16 + (lane & 15);
                uint32_t off = sw64((uint32_t)(br * 64 + koff));
                uint32_t bh[4], bl[4];
                ldsm4(bHs + off, bh);
                ldsm4(bLs + off, bl);
#pragma unroll
                for (int tm = 0; tm < 4; tm++) {
                    mma16816(acc[tm][2*u],   ah[tm], bh[0], bh[2]);
                    mma16816(acc[tm][2*u+1], ah[tm], bh[1], bh[3]);
                }
#pragma unroll
                for (int tm = 0; tm < 4; tm++) {
                    mma16816(acc[tm][2*u],   ah[tm], bl[0], bl[2]);
                    mma16816(acc[tm][2*u+1], ah[tm], bl[1], bl[3]);
                }
#pragma unroll
                for (int tm = 0; tm < 4; tm++) {
                    mma16816(acc[tm][2*u],   al[tm], bh[0], bh[2]);
                    mma16816(acc[tm][2*u+1], al[tm], bh[1], bh[3]);
                }
            }
        }
        if (pre) CPC();
    }

    // ---- epilogue ----
#pragma unroll
    for (int tm = 0; tm < 4; tm++) {
#pragma unroll
        for (int j = 0; j < 4; j++) {
            int nb = n0 + wn * 32 + j * 8 + (lane & 3) * 2;
            float2 bv = *(const float2*)&bias[nb];
#pragma unroll
            for (int half = 0; half < 2; half++) {
                int m = m0 + wm * 64 + tm * 16 + (lane >> 2) + half * 8;
                float v0 = acc[tm][j][half * 2 + 0] + bv.x;
                float v1 = acc[tm][j][half * 2 + 1] + bv.y;
                if (MODE == 0) {
                    int bb = m >> 11, nn = m & (N_ - 1);
                    int which = nb >> 10, e = nb & 1023;
                    int h = e >> 6, d = e & 63;
                    if (which == 0) { v0 *= SCALE_; v1 *= SCALE_; }  // pre-scale q (exact, 2^-3)
                    __nv_bfloat16* dh = (which == 0) ? g_qh : (which == 1) ? g_kh : g_vh;
                    __nv_bfloat16* dl = (which == 0) ? g_ql : (which == 1) ? g_kl : g_vl;
                    size_t idx = (((size_t)bb * H_ + h) * N_ + nn) * D_ + d;
                    *(uint32_t*)&dh[idx] = pack_hi2(v0, v1);
                    *(uint32_t*)&dl[idx] = pack_lo2(v0, v1);
                } else {
                    float2 v = {v0, v1};
                    *(float2*)&C[(size_t)m * Nout + nb] = v;
                }
            }
        }
    }
}

// =====================================================================
// Flash attention, mma.sync bf16x3, single-buffer KV, 3 CTAs/SM.
// Block = 128 threads (4 warps), q-tile 64 rows (16 per warp), D=64.
// smem: P hi/lo (16KB) + (Kh,Kl,Vh,Vl) (32KB) = 48KB (+pad).
// Heavy q-tiles launch first (reversed blockIdx).
// =====================================================================
#define ATT_SMEM (1024 + 16384 + 32768)

__global__ __launch_bounds__(128, 3)
void attention_kernel()
{
    char* sm = (char*)(((uintptr_t)dyn_smem + 1023) & ~(uintptr_t)1023);
    uint32_t sb = smem_u32(sm);
    const uint32_t Pha = sb;
    const uint32_t Pla = sb + 8192;
    const uint32_t KVb = sb + 16384;   // Kh, Kl, Vh, Vl (8KB each)

    int tid = threadIdx.x;
    int lane = tid & 31;
    int wid = tid >> 5;
    int qt = gridDim.x - 1 - blockIdx.x;   // heavy tiles first
    int bh = blockIdx.y;
    size_t base = (size_t)bh * N_ * D_;

    // prologue: Q tile into P region
#pragma unroll
    for (int l = 0; l < 4; l++) {
        int idx = tid + l * 128;
        int row = idx >> 3, seg = idx & 7;
        size_t go = base + (size_t)(qt * 64 + row) * D_ + seg * 8;
        uint32_t off = sw128((uint32_t)(row * 128 + seg * 16));
        cpa16(Pha + off, g_qh + go);
        cpa16(Pla + off, g_ql + go);
    }
    CPC(); CPW(0);
    __syncthreads();

    // Q fragments (q pre-scaled by SCALE_ in gemm<0> epilogue)
    uint32_t qh[4][4], qlr[4][4];
    int ar = wid * 16 + (lane & 15);
#pragma unroll
    for (int ks = 0; ks < 4; ks++) {
        uint32_t off = sw128((uint32_t)(ar * 128 + (ks * 16 + (lane >> 4) * 8) * 2));
        ldsm4(Pha + off, qh[ks]);
        ldsm4(Pla + off, qlr[ks]);
    }

    float o[8][4];
#pragma unroll
    for (int j = 0; j < 8; j++)
#pragma unroll
        for (int e = 0; e < 4; e++) o[j][e] = 0.f;
    float m0r = -1e30f, m1r = -1e30f, l0 = 0.f, l1 = 0.f;

    int rowl0 = wid * 16 + (lane >> 2);
    int rowl1 = rowl0 + 8;

    for (int kt = 0; kt <= qt; kt++) {
        __syncthreads();            // all warps done reading previous K/V & P
#pragma unroll
        for (int l = 0; l < 4; l++) {
            int idx = tid + l * 128;
            int row = idx >> 3, seg = idx & 7;
            size_t go = base + (size_t)(kt * 64 + row) * D_ + seg * 8;
            uint32_t off = sw128((uint32_t)(row * 128 + seg * 16));
            cpa16(KVb + off, g_kh + go);
            cpa16(KVb + 8192 + off, g_kl + go);
            cpa16(KVb + 16384 + off, g_vh + go);
            cpa16(KVb + 24576 + off, g_vl + go);
        }
        CPC(); CPW(0);
        __syncthreads();            // K/V visible to all threads

        uint32_t Kh = KVb;
        uint32_t Kl = KVb + 8192;
        uint32_t Vh = KVb + 16384;
        uint32_t Vl = KVb + 24576;

        // ---- S = Q K^T (3-term, pass-reordered) ----
        float sc[8][4];
#pragma unroll
        for (int j = 0; j < 8; j++)
#pragma unroll
            for (int e = 0; e < 4; e++) sc[j][e] = 0.f;

#pragma unroll
        for (int ks = 0; ks < 4; ks++) {
            int koff = (ks * 16 + (lane >> 4) * 8) * 2;
            uint32_t kh4[4][4], kl4[4][4];
#pragma unroll
            for (int u = 0; u < 4; u++) {
                int br = u * 16 + (lane & 15);
                uint32_t off = sw128((uint32_t)(br * 128 + koff));
                ldsm4(Kh + off, kh4[u]);
                ldsm4(Kl + off, kl4[u]);
            }
#pragma unroll
            for (int u = 0; u < 4; u++) {
                mma16816(sc[2*u],   qh[ks], kh4[u][0], kh4[u][2]);
                mma16816(sc[2*u+1], qh[ks], kh4[u][1], kh4[u][3]);
            }
#pragma unroll
            for (int u = 0; u < 4; u++) {
                mma16816(sc[2*u],   qh[ks], kl4[u][0], kl4[u][2]);
                mma16816(sc[2*u+1], qh[ks], kl4[u][1], kl4[u][3]);
            }
#pragma unroll
            for (int u = 0; u < 4; u++) {
                mma16816(sc[2*u],   qlr[ks], kh4[u][0], kh4[u][2]);
                mma16816(sc[2*u+1], qlr[ks], kh4[u][1], kh4[u][3]);
            }
        }

        if (kt == qt) {
#pragma unroll
            for (int j = 0; j < 8; j++) {
                int c = j * 8 + (lane & 3) * 2;
                if (c     > rowl0) sc[j][0] = -1e30f;
                if (c + 1 > rowl0) sc[j][1] = -1e30f;
                if (c     > rowl1) sc[j][2] = -1e30f;
                if (c + 1 > rowl1) sc[j][3] = -1e30f;
            }
        }

        // ---- online softmax ----
        float t0 = -1e30f, t1 = -1e30f;
#pragma unroll
        for (int j = 0; j < 8; j++) {
            t0 = fmaxf(t0, fmaxf(sc[j][0], sc[j][1]));
            t1 = fmaxf(t1, fmaxf(sc[j][2], sc[j][3]));
        }
        t0 = fmaxf(t0, __shfl_xor_sync(0xffffffff, t0, 1));
        t0 = fmaxf(t0, __shfl_xor_sync(0xffffffff, t0, 2));
        t1 = fmaxf(t1, __shfl_xor_sync(0xffffffff, t1, 1));
        t1 = fmaxf(t1, __shfl_xor_sync(0xffffffff, t1, 2));
        float nm0 = fmaxf(m0r, t0), nm1 = fmaxf(m1r, t1);
        float f0 = __expf(m0r - nm0), f1 = __expf(m1r - nm1);
        m0r = nm0; m1r = nm1;

        float s0 = 0.f, s1 = 0.f;
#pragma unroll
        for (int j = 0; j < 8; j++) {
            float p0 = __expf(sc[j][0] - nm0);
            float p1 = __expf(sc[j][1] - nm0);
            float p2 = __expf(sc[j][2] - nm1);
            float p3 = __expf(sc[j][3] - nm1);
            s0 += p0 + p1; s1 += p2 + p3;
            uint32_t coff = (uint32_t)(j * 16 + (lane & 3) * 4);
            uint32_t off0 = sw128((uint32_t)(rowl0 * 128) + coff);
            uint32_t off1 = sw128((uint32_t)(rowl1 * 128) + coff);
            *(uint32_t*)(sm + (Pha - sb) + off0) = pack_hi2(p0, p1);
            *(uint32_t*)(sm + (Pla - sb) + off0) = pack_lo2(p0, p1);
            *(uint32_t*)(sm + (Pha - sb) + off1) = pack_hi2(p2, p3);
            *(uint32_t*)(sm + (Pla - sb) + off1) = pack_lo2(p2, p3);
            o[j][0] *= f0; o[j][1] *= f0; o[j][2] *= f1; o[j][3] *= f1;
        }
        s0 += __shfl_xor_sync(0xffffffff, s0, 1);
        s0 += __shfl_xor_sync(0xffffffff, s0, 2);
        s1 += __shfl_xor_sync(0xffffffff, s1, 1);
        s1 += __shfl_xor_sync(0xffffffff, s1, 2);
        l0 = l0 * f0 + s0;
        l1 = l1 * f1 + s1;
        __syncwarp();      // P writes (warp-local rows) visible before ldsm

        // ---- O += P V (3-term, pass-reordered) ----
#pragma unroll
        for (int ks = 0; ks < 4; ks++) {
            uint32_t offp = sw128((uint32_t)(ar * 128 + (ks * 16 + (lane >> 4) * 8) * 2));
            uint32_t ph4[4], pl4[4];
            ldsm4(Pha + offp, ph4);
            ldsm4(Pla + offp, pl4);
            uint32_t vh4[4][4], vl4[4][4];
#pragma unroll
            for (int u = 0; u < 4; u++) {
                int vr = ks * 16 + ((lane >> 4) << 3) + (lane & 7);
                int vc = u * 16 + ((lane >> 3) & 1) * 8;
                uint32_t offv = sw128((uint32_t)(vr * 128 + vc * 2));
                ldsm4t(Vh + offv, vh4[u]);
                ldsm4t(Vl + offv, vl4[u]);
            }
#pragma unroll
            for (int u = 0; u < 4; u++) {
                mma16816(o[2*u],   ph4, vh4[u][0], vh4[u][2]);
                mma16816(o[2*u+1], ph4, vh4[u][1], vh4[u][3]);
            }
#pragma unroll
            for (int u = 0; u < 4; u++) {
                mma16816(o[2*u],   ph4, vl4[u][0], vl4[u][2]);
                mma16816(o[2*u+1], ph4, vl4[u][1], vl4[u][3]);
            }
#pragma unroll
            for (int u = 0; u < 4; u++) {
                mma16816(o[2*u],   pl4, vh4[u][0], vh4[u][2]);
                mma16816(o[2*u+1], pl4, vh4[u][1], vh4[u][3]);
            }
        }
    }

    // ---- epilogue ----
    float inv0 = 1.f / l0, inv1 = 1.f / l1;
    int b = bh >> 4, h = bh & 15;
    int n0g = qt * 64 + rowl0;
#pragma unroll
    for (int j = 0; j < 8; j++) {
        int d = h * 64 + j * 8 + (lane & 3) * 2;
        size_t i0 = ((size_t)b * N_ + n0g) * E_ + d;
        size_t i1 = ((size_t)b * N_ + n0g + 8) * E_ + d;
        *(uint32_t*)&g_at_hi[i0] = pack_hi2(o[j][0] * inv0, o[j][1] * inv0);
        *(uint32_t*)&g_at_lo[i0] = pack_lo2(o[j][0] * inv0, o[j][1] * inv0);
        *(uint32_t*)&g_at_hi[i1] = pack_hi2(o[j][2] * inv1, o[j][3] * inv1);
        *(uint32_t*)&g_at_lo[i1] = pack_lo2(o[j][2] * inv1, o[j][3] * inv1);
    }
}

// =====================================================================
// launch
// =====================================================================
extern "C" void kernel_launch(void* const* d_in, const int* in_sizes, int n_in,
                              void* d_out, int out_size)
{
    const float* x     = (const float*)d_in[0];
    const float* qkv_w = (const float*)d_in[1];
    const float* qkv_b = (const float*)d_in[2];
    const float* out_w = (const float*)d_in[3];
    const float* out_b = (const float*)d_in[4];
    float* out = (float*)d_out;

    const int M = B_ * N_;
    const int gemm_smem = 2 * G_STAGE + 1024;    // 65 KB -> 2 CTAs/SM

    cudaFuncSetAttribute(gemm_mma<0>, cudaFuncAttributeMaxDynamicSharedMemorySize, gemm_smem);
    cudaFuncSetAttribute(gemm_mma<1>, cudaFuncAttributeMaxDynamicSharedMemorySize, gemm_smem);
    cudaFuncSetAttribute(attention_kernel, cudaFuncAttributeMaxDynamicSharedMemorySize, ATT_SMEM);

    split_kernel<0><<<(M * E_ / 4 + 255) / 256, 256>>>(x, M * E_ / 4);
    split_kernel<1><<<(3 * E_ * E_ / 4 + 255) / 256, 256>>>(qkv_w, 3 * E_ * E_ / 4);
    split_kernel<2><<<(E_ * E_ / 4 + 255) / 256, 256>>>(out_w, E_ * E_ / 4);

    gemm_mma<0><<<dim3(3 * E_ / 128, M / 128), 256, gemm_smem>>>(qkv_b, nullptr, E_, 3 * E_);

    attention_kernel<<<dim3(N_ / 64, B_ * H_), 128, ATT_SMEM>>>();

    gemm_mma<1><<<dim3(E_ / 128, M / 128), 256, gemm_smem>>>(out_b, out, E_, E_);
}

// round 9
// speedup vs baseline: 1.3670x; 1.3670x over previous
#include <cuda_runtime.h>
#include <cuda_fp16.h>
#include <cstdint>

// ---------------- problem constants ----------------
#define B_   2
#define N_   2048
#define E_   1024
#define H_   16
#define D_   64
#define SCALE_ 0.125f   // 64^-0.5

// ---------------- device scratch (no allocs allowed) ----------------
__device__ __half g_x_hi[(size_t)B_*N_*E_];            // x rounded (2-term QKV)
__device__ __half g_w_hi[(size_t)3*E_*E_];
__device__ __half g_w_lo[(size_t)3*E_*E_];
__device__ __half g_ow_hi[(size_t)E_*E_];
__device__ __half g_ow_lo[(size_t)E_*E_];
__device__ __half g_qh[(size_t)B_*H_*N_*D_];           // pre-scaled by SCALE_
__device__ __half g_ql[(size_t)B_*H_*N_*D_];
__device__ __half g_kh[(size_t)B_*H_*N_*D_];
__device__ __half g_kl[(size_t)B_*H_*N_*D_];
__device__ __half g_vh[(size_t)B_*H_*N_*D_];
__device__ __half g_vl[(size_t)B_*H_*N_*D_];
__device__ __half g_at_hi[(size_t)B_*N_*E_];           // attention out rounded

// =====================================================================
// helpers
// =====================================================================
__device__ __forceinline__ uint32_t smem_u32(const void* p) {
    uint32_t a;
    asm("{ .reg .u64 t; cvta.to.shared.u64 t, %1; cvt.u32.u64 %0, t; }" : "=r"(a) : "l"(p));
    return a;
}
__device__ __forceinline__ uint32_t sw128(uint32_t off) { return off ^ ((off >> 3) & 0x70); }

__device__ __forceinline__ void cpa16(uint32_t dst, const void* src) {
    asm volatile("cp.async.cg.shared.global [%0], [%1], 16;" :: "r"(dst), "l"(src));
}
#define CPC() asm volatile("cp.async.commit_group;" ::: "memory")
#define CPW(n) asm volatile("cp.async.wait_group %0;" :: "n"(n) : "memory")

__device__ __forceinline__ void ldsm4(uint32_t addr, uint32_t* r) {
    asm volatile("ldmatrix.sync.aligned.m8n8.x4.shared.b16 {%0,%1,%2,%3}, [%4];"
        : "=r"(r[0]), "=r"(r[1]), "=r"(r[2]), "=r"(r[3]) : "r"(addr));
}
__device__ __forceinline__ void ldsm4t(uint32_t addr, uint32_t* r) {
    asm volatile("ldmatrix.sync.aligned.m8n8.x4.trans.shared.b16 {%0,%1,%2,%3}, [%4];"
        : "=r"(r[0]), "=r"(r[1]), "=r"(r[2]), "=r"(r[3]) : "r"(addr));
}
// fp16 MMA, fp32 accumulate
__device__ __forceinline__ void mma16816(float* c, const uint32_t* a, uint32_t b0, uint32_t b1) {
    asm("mma.sync.aligned.m16n8k16.row.col.f32.f16.f16.f32 "
        "{%0,%1,%2,%3},{%4,%5,%6,%7},{%8,%9},{%0,%1,%2,%3};"
        : "+f"(c[0]), "+f"(c[1]), "+f"(c[2]), "+f"(c[3])
        : "r"(a[0]), "r"(a[1]), "r"(a[2]), "r"(a[3]), "r"(b0), "r"(b1));
}

__device__ __forceinline__ uint32_t pack_h2(float v0, float v1) {
    __half2 h = __floats2half2_rn(v0, v1);
    return *(uint32_t*)&h;
}
__device__ __forceinline__ uint32_t pack_l2(float v0, float v1) {
    __half h0 = __float2half_rn(v0), h1 = __float2half_rn(v1);
    __half2 l = __halves2half2(__float2half_rn(v0 - __half2float(h0)),
                               __float2half_rn(v1 - __half2float(h1)));
    return *(uint32_t*)&l;
}

// =====================================================================
// split kernels
// W=0: x -> hi only.  W=1: qkv_w -> hi/lo.  W=2: out_w -> hi/lo.
// =====================================================================
template<int W>
__global__ void split_kernel(const float* __restrict__ src, int n4)
{
    int i = blockIdx.x * blockDim.x + threadIdx.x;
    if (i >= n4) return;
    float4 a = *(const float4*)&src[(size_t)i * 4];
    uint2 hv = {pack_h2(a.x, a.y), pack_h2(a.z, a.w)};
    if (W == 0) {
        *(uint2*)&g_x_hi[(size_t)i * 4] = hv;
    } else {
        __half* hi = (W == 1) ? g_w_hi : g_ow_hi;
        __half* lo = (W == 1) ? g_w_lo : g_ow_lo;
        uint2 lv = {pack_l2(a.x, a.y), pack_l2(a.z, a.w)};
        *(uint2*)&hi[(size_t)i * 4] = hv;
        *(uint2*)&lo[(size_t)i * 4] = lv;
    }
}

// =====================================================================
// mma.sync GEMM (NT), fp16 2-term (A rounded, B split):
// C[m,n] = sum_k A[m,k]*Bw[n,k] + bias[n]
// BM=128, BN=256, BK=64. 256 threads, 8 warps (2x4), warp tile 64x64.
// smem stage: Ah(16K) + Bh(32K) + Bl(32K) = 80KB, double buffered.
// MODE 0: epilogue -> q/k/v hi/lo (scatter [B,H,N,D], q scaled); MODE 1: fp32 C.
// =====================================================================
#define GA_TILE 16384                // A: 128 rows * 128B
#define GB_TILE 32768                // B: 256 rows * 128B
#define GT_STAGE (GA_TILE + 2 * GB_TILE)       // 80KB

extern __shared__ __align__(16) char dyn_smem[];

template<int MODE>
__global__ __launch_bounds__(256, 1)
void gemm_mma(const float* __restrict__ bias, float* __restrict__ C, int K, int Nout)
{
    const __half* Ah = (MODE == 0) ? g_x_hi : g_at_hi;
    const __half* Bh = (MODE == 0) ? g_w_hi : g_ow_hi;
    const __half* Bl = (MODE == 0) ? g_w_lo : g_ow_lo;

    char* sm = (char*)(((uintptr_t)dyn_smem + 1023) & ~(uintptr_t)1023);
    uint32_t sb = smem_u32(sm);

    int tid = threadIdx.x;
    int lane = tid & 31;
    int wid = tid >> 5;              // 0..7
    int wm = wid >> 2;               // 0..1 -> rows wm*64
    int wn = wid & 3;                // 0..3 -> cols wn*64
    int m0 = blockIdx.y * 128;
    int n0 = blockIdx.x * 256;

    float acc[4][8][4];
#pragma unroll
    for (int a = 0; a < 4; a++)
#pragma unroll
        for (int b = 0; b < 8; b++)
#pragma unroll
            for (int c = 0; c < 4; c++) acc[a][b][c] = 0.f;

    // issue quarter q (0..3) of the loads for stage s (5 cpa16/thread)
    auto load_quarter = [&](int s, int k0, int q) {
        uint32_t st = sb + s * GT_STAGE;
        {
            int idx = tid + q * 256;            // A: 1 of 4 chunks
            int row = idx >> 3, seg = idx & 7;
            uint32_t off = sw128((uint32_t)(row * 128 + seg * 16));
            size_t go = (size_t)(m0 + row) * K + k0 + seg * 8;
            cpa16(st + off, Ah + go);
        }
#pragma unroll
        for (int l2 = 0; l2 < 2; l2++) {        // B: 2 of 8 chunks (hi+lo)
            int idx = tid + (q * 2 + l2) * 256;
            int row = idx >> 3, seg = idx & 7;
            uint32_t off = sw128((uint32_t)(row * 128 + seg * 16));
            size_t go = (size_t)(n0 + row) * K + k0 + seg * 8;
            cpa16(st + GA_TILE + off, Bh + go);
            cpa16(st + GA_TILE + GB_TILE + off, Bl + go);
        }
    };

    const int NIT = K / 64;
#pragma unroll
    for (int q = 0; q < 4; q++) load_quarter(0, 0, q);
    CPC();

    for (int it = 0; it < NIT; it++) {
        int s = it & 1;
        CPW(0);
        __syncthreads();

        uint32_t aH = sb + s * GT_STAGE;
        uint32_t bHs = aH + GA_TILE;
        uint32_t bLs = bHs + GB_TILE;
        bool pre = (it + 1 < NIT);

#pragma unroll
        for (int ks = 0; ks < 4; ks++) {
            if (pre) load_quarter(s ^ 1, (it + 1) * 64, ks);

            int koff = (ks * 16 + (lane >> 4) * 8) * 2;
            uint32_t ah[4][4];
#pragma unroll
            for (int tm = 0; tm < 4; tm++) {
                int ar = wm * 64 + tm * 16 + (lane & 15);
                uint32_t off = sw128((uint32_t)(ar * 128 + koff));
                ldsm4(aH + off, ah[tm]);
            }
#pragma unroll
            for (int u = 0; u < 4; u++) {
                int br = wn * 64 + u * 16 + (lane & 15);
                uint32_t off = sw128((uint32_t)(br * 128 + koff));
                uint32_t bh[4], bl[4];
                ldsm4(bHs + off, bh);
                ldsm4(bLs + off, bl);
#pragma unroll
                for (int tm = 0; tm < 4; tm++) {
                    mma16816(acc[tm][2*u],   ah[tm], bh[0], bh[2]);
                    mma16816(acc[tm][2*u+1], ah[tm], bh[1], bh[3]);
                }
#pragma unroll
                for (int tm = 0; tm < 4; tm++) {
                    mma16816(acc[tm][2*u],   ah[tm], bl[0], bl[2]);
                    mma16816(acc[tm][2*u+1], ah[tm], bl[1], bl[3]);
                }
            }
        }
        if (pre) CPC();
    }

    // ---- epilogue ----
#pragma unroll
    for (int tm = 0; tm < 4; tm++) {
#pragma unroll
        for (int j = 0; j < 8; j++) {
            int nb = n0 + wn * 64 + j * 8 + (lane & 3) * 2;
            float2 bv = *(const float2*)&bias[nb];
#pragma unroll
            for (int half = 0; half < 2; half++) {
                int m = m0 + wm * 64 + tm * 16 + (lane >> 2) + half * 8;
                float v0 = acc[tm][j][half * 2 + 0] + bv.x;
                float v1 = acc[tm][j][half * 2 + 1] + bv.y;
                if (MODE == 0) {
                    int bb = m >> 11, nn = m & (N_ - 1);
                    int which = nb >> 10, e = nb & 1023;
                    int h = e >> 6, d = e & 63;
                    if (which == 0) { v0 *= SCALE_; v1 *= SCALE_; }  // pre-scale q (exact, 2^-3)
                    __half* dh = (which == 0) ? g_qh : (which == 1) ? g_kh : g_vh;
                    __half* dl = (which == 0) ? g_ql : (which == 1) ? g_kl : g_vl;
                    size_t idx = (((size_t)bb * H_ + h) * N_ + nn) * D_ + d;
                    *(uint32_t*)&dh[idx] = pack_h2(v0, v1);
                    *(uint32_t*)&dl[idx] = pack_l2(v0, v1);
                } else {
                    float2 v = {v0, v1};
                    *(float2*)&C[(size_t)m * Nout + nb] = v;
                }
            }
        }
    }
}

// =====================================================================
// Flash attention, fp16: S = QK^T 3-term, O += P V 2-term (P rounded).
// Block = 128 threads (4 warps), q-tile 64 rows, D=64.
// smem: Ph(8K) + Qlo scratch(8K) + 2 stages x (Kh,Kl,Vh,Vl) (64KB).
// Heavy q-tiles launch first (reversed blockIdx).
// =====================================================================
#define AKV_STAGE 32768
#define ATT_SMEM (1024 + 16384 + 2 * AKV_STAGE)

__global__ __launch_bounds__(128, 2)
void attention_kernel()
{
    char* sm = (char*)(((uintptr_t)dyn_smem + 1023) & ~(uintptr_t)1023);
    uint32_t sb = smem_u32(sm);
    const uint32_t Pha = sb;           // P hi (mainloop) / Q hi (prologue)
    const uint32_t Qla = sb + 8192;    // Q lo (prologue only)
    const uint32_t KVb = sb + 16384;   // stage s: Kh, Kl, Vh, Vl (8KB each)

    int tid = threadIdx.x;
    int lane = tid & 31;
    int wid = tid >> 5;
    int qt = gridDim.x - 1 - blockIdx.x;   // heavy tiles first
    int bh = blockIdx.y;
    size_t base = (size_t)bh * N_ * D_;

    // prologue: Q tile (hi/lo) + first K/V stage
#pragma unroll
    for (int l = 0; l < 4; l++) {
        int idx = tid + l * 128;
        int row = idx >> 3, seg = idx & 7;
        size_t go = base + (size_t)(qt * 64 + row) * D_ + seg * 8;
        uint32_t off = sw128((uint32_t)(row * 128 + seg * 16));
        cpa16(Pha + off, g_qh + go);
        cpa16(Qla + off, g_ql + go);
    }
    CPC();

    auto load_kv = [&](int s, int kt) {
        uint32_t kvb = KVb + s * AKV_STAGE;
#pragma unroll
        for (int l = 0; l < 4; l++) {
            int idx = tid + l * 128;
            int row = idx >> 3, seg = idx & 7;
            size_t go = base + (size_t)(kt * 64 + row) * D_ + seg * 8;
            uint32_t off = sw128((uint32_t)(row * 128 + seg * 16));
            cpa16(kvb + off, g_kh + go);
            cpa16(kvb + 8192 + off, g_kl + go);
            cpa16(kvb + 16384 + off, g_vh + go);
            cpa16(kvb + 24576 + off, g_vl + go);
        }
        CPC();
    };
    load_kv(0, 0);

    CPW(0);
    __syncthreads();

    // Q fragments (q pre-scaled by SCALE_)
    uint32_t qh[4][4], qlr[4][4];
    int ar = wid * 16 + (lane & 15);
#pragma unroll
    for (int ks = 0; ks < 4; ks++) {
        uint32_t off = sw128((uint32_t)(ar * 128 + (ks * 16 + (lane >> 4) * 8) * 2));
        ldsm4(Pha + off, qh[ks]);
        ldsm4(Qla + off, qlr[ks]);
    }

    float o[8][4];
#pragma unroll
    for (int j = 0; j < 8; j++)
#pragma unroll
        for (int e = 0; e < 4; e++) o[j][e] = 0.f;
    float m0r = -1e30f, m1r = -1e30f, l0 = 0.f, l1 = 0.f;

    int rowl0 = wid * 16 + (lane >> 2);
    int rowl1 = rowl0 + 8;

    for (int kt = 0; kt <= qt; kt++) {
        int s = kt & 1;
        __syncthreads();
        if (kt < qt) load_kv(s ^ 1, kt + 1);
        if (kt < qt) { CPW(1); } else { CPW(0); }
        __syncthreads();

        uint32_t Kh = KVb + s * AKV_STAGE;
        uint32_t Kl = Kh + 8192;
        uint32_t Vh = Kh + 16384;
        uint32_t Vl = Kh + 24576;

        // ---- S = Q K^T (3-term fp16) ----
        float sc[8][4];
#pragma unroll
        for (int j = 0; j < 8; j++)
#pragma unroll
            for (int e = 0; e < 4; e++) sc[j][e] = 0.f;

#pragma unroll
        for (int ks = 0; ks < 4; ks++) {
            int koff = (ks * 16 + (lane >> 4) * 8) * 2;
            uint32_t kh4[4][4], kl4[4][4];
#pragma unroll
            for (int u = 0; u < 4; u++) {
                int br = u * 16 + (lane & 15);
                uint32_t off = sw128((uint32_t)(br * 128 + koff));
                ldsm4(Kh + off, kh4[u]);
                ldsm4(Kl + off, kl4[u]);
            }
#pragma unroll
            for (int u = 0; u < 4; u++) {
                mma16816(sc[2*u],   qh[ks], kh4[u][0], kh4[u][2]);
                mma16816(sc[2*u+1], qh[ks], kh4[u][1], kh4[u][3]);
            }
#pragma unroll
            for (int u = 0; u < 4; u++) {
                mma16816(sc[2*u],   qh[ks], kl4[u][0], kl4[u][2]);
                mma16816(sc[2*u+1], qh[ks], kl4[u][1], kl4[u][3]);
            }
#pragma unroll
            for (int u = 0; u < 4; u++) {
                mma16816(sc[2*u],   qlr[ks], kh4[u][0], kh4[u][2]);
                mma16816(sc[2*u+1], qlr[ks], kh4[u][1], kh4[u][3]);
            }
        }

        if (kt == qt) {
#pragma unroll
            for (int j = 0; j < 8; j++) {
                int c = j * 8 + (lane & 3) * 2;
                if (c     > rowl0) sc[j][0] = -1e30f;
                if (c + 1 > rowl0) sc[j][1] = -1e30f;
                if (c     > rowl1) sc[j][2] = -1e30f;
                if (c + 1 > rowl1) sc[j][3] = -1e30f;
            }
        }

        // ---- online softmax ----
        float t0 = -1e30f, t1 = -1e30f;
#pragma unroll
        for (int j = 0; j < 8; j++) {
            t0 = fmaxf(t0, fmaxf(sc[j][0], sc[j][1]));
            t1 = fmaxf(t1, fmaxf(sc[j][2], sc[j][3]));
        }
        t0 = fmaxf(t0, __shfl_xor_sync(0xffffffff, t0, 1));
        t0 = fmaxf(t0, __shfl_xor_sync(0xffffffff, t0, 2));
        t1 = fmaxf(t1, __shfl_xor_sync(0xffffffff, t1, 1));
        t1 = fmaxf(t1, __shfl_xor_sync(0xffffffff, t1, 2));
        float nm0 = fmaxf(m0r, t0), nm1 = fmaxf(m1r, t1);
        float f0 = __expf(m0r - nm0), f1 = __expf(m1r - nm1);
        m0r = nm0; m1r = nm1;

        float s0 = 0.f, s1 = 0.f;
#pragma unroll
        for (int j = 0; j < 8; j++) {
            float p0 = __expf(sc[j][0] - nm0);
            float p1 = __expf(sc[j][1] - nm0);
            float p2 = __expf(sc[j][2] - nm1);
            float p3 = __expf(sc[j][3] - nm1);
            s0 += p0 + p1; s1 += p2 + p3;
            uint32_t coff = (uint32_t)(j * 16 + (lane & 3) * 4);
            uint32_t off0 = sw128((uint32_t)(rowl0 * 128) + coff);
            uint32_t off1 = sw128((uint32_t)(rowl1 * 128) + coff);
            *(uint32_t*)(sm + off0) = pack_h2(p0, p1);   // P hi only (2-term PV)
            *(uint32_t*)(sm + off1) = pack_h2(p2, p3);
            o[j][0] *= f0; o[j][1] *= f0; o[j][2] *= f1; o[j][3] *= f1;
        }
        s0 += __shfl_xor_sync(0xffffffff, s0, 1);
        s0 += __shfl_xor_sync(0xffffffff, s0, 2);
        s1 += __shfl_xor_sync(0xffffffff, s1, 1);
        s1 += __shfl_xor_sync(0xffffffff, s1, 2);
        l0 = l0 * f0 + s0;
        l1 = l1 * f1 + s1;
        __syncwarp();      // P writes (warp-local rows) visible before ldsm

        // ---- O += P V (2-term: Ph*Vh + Ph*Vl) ----
#pragma unroll
        for (int ks = 0; ks < 4; ks++) {
            uint32_t offp = sw128((uint32_t)(ar * 128 + (ks * 16 + (lane >> 4) * 8) * 2));
            uint32_t ph4[4];
            ldsm4(Pha + offp, ph4);
            uint32_t vh4[4][4], vl4[4][4];
#pragma unroll
            for (int u = 0; u < 4; u++) {
                int vr = ks * 16 + ((lane >> 4) << 3) + (lane & 7);
                int vc = u * 16 + ((lane >> 3) & 1) * 8;
                uint32_t offv = sw128((uint32_t)(vr * 128 + vc * 2));
                ldsm4t(Vh + offv, vh4[u]);
                ldsm4t(Vl + offv, vl4[u]);
            }
#pragma unroll
            for (int u = 0; u < 4; u++) {
                mma16816(o[2*u],   ph4, vh4[u][0], vh4[u][2]);
                mma16816(o[2*u+1], ph4, vh4[u][1], vh4[u][3]);
            }
#pragma unroll
            for (int u = 0; u < 4; u++) {
                mma16816(o[2*u],   ph4, vl4[u][0], vl4[u][2]);
                mma16816(o[2*u+1], ph4, vl4[u][1], vl4[u][3]);
            }
        }
    }

    // ---- epilogue: normalize + write fp16 hi [B,N,E] ----
    float inv0 = 1.f / l0, inv1 = 1.f / l1;
    int b = bh >> 4, h = bh & 15;
    int n0g = qt * 64 + rowl0;
#pragma unroll
    for (int j = 0; j < 8; j++) {
        int d = h * 64 + j * 8 + (lane & 3) * 2;
        size_t i0 = ((size_t)b * N_ + n0g) * E_ + d;
        size_t i1 = ((size_t)b * N_ + n0g + 8) * E_ + d;
        *(uint32_t*)&g_at_hi[i0] = pack_h2(o[j][0] * inv0, o[j][1] * inv0);
        *(uint32_t*)&g_at_hi[i1] = pack_h2(o[j][2] * inv1, o[j][3] * inv1);
    }
}

// =====================================================================
// launch
// =====================================================================
extern "C" void kernel_launch(void* const* d_in, const int* in_sizes, int n_in,
                              void* d_out, int out_size)
{
    const float* x     = (const float*)d_in[0];
    const float* qkv_w = (const float*)d_in[1];
    const float* qkv_b = (const float*)d_in[2];
    const float* out_w = (const float*)d_in[3];
    const float* out_b = (const float*)d_in[4];
    float* out = (float*)d_out;

    const int M = B_ * N_;
    const int gemm_smem = 2 * GT_STAGE + 1024;   // 161 KB

    cudaFuncSetAttribute(gemm_mma<0>, cudaFuncAttributeMaxDynamicSharedMemorySize, gemm_smem);
    cudaFuncSetAttribute(gemm_mma<1>, cudaFuncAttributeMaxDynamicSharedMemorySize, gemm_smem);
    cudaFuncSetAttribute(attention_kernel, cudaFuncAttributeMaxDynamicSharedMemorySize, ATT_SMEM);

    split_kernel<0><<<(M * E_ / 4 + 255) / 256, 256>>>(x, M * E_ / 4);
    split_kernel<1><<<(3 * E_ * E_ / 4 + 255) / 256, 256>>>(qkv_w, 3 * E_ * E_ / 4);
    split_kernel<2><<<(E_ * E_ / 4 + 255) / 256, 256>>>(out_w, E_ * E_ / 4);

    gemm_mma<0><<<dim3(3 * E_ / 256, M / 128), 256, gemm_smem>>>(qkv_b, nullptr, E_, 3 * E_);

    attention_kernel<<<dim3(N_ / 64, B_ * H_), 128, ATT_SMEM>>>();

    gemm_mma<1><<<dim3(E_ / 256, M / 128), 256, gemm_smem>>>(out_b, out, E_, E_);
}